// round 14
// baseline (speedup 1.0000x reference)
#include <cuda_runtime.h>
#include <cuda_bf16.h>
#include <cstdint>
#include <cstddef>

typedef unsigned int u32;
typedef unsigned long long u64;

#define Bb   8
#define Nn   256
#define Mm   512
#define EXTm 768
#define Ee   1024
#define Hh   32
#define SCALING 0.17677669529663687f
#define NEGINF  -3.402823466e38f

// ---------------- scratch ----------------
__device__ float4 g_pd[(size_t)Bb*Nn*EXTm];
__device__ __nv_bfloat16 g_ah[(size_t)8192*Ee];
__device__ __nv_bfloat16 g_al[(size_t)8192*Ee];
__device__ __nv_bfloat16 g_wh[(size_t)6*Ee*Ee];
__device__ __nv_bfloat16 g_wl[(size_t)6*Ee*Ee];
__device__ __nv_bfloat16 g_qh[(size_t)Bb*Nn*Ee],  g_ql[(size_t)Bb*Nn*Ee];
__device__ __nv_bfloat16 g_kh[(size_t)Bb*EXTm*Ee], g_kl[(size_t)Bb*EXTm*Ee];
__device__ __nv_bfloat16 g_vh[(size_t)Bb*EXTm*Ee], g_vl[(size_t)Bb*EXTm*Ee];
__device__ __nv_bfloat16 g_veh[(size_t)Bb*EXTm*Ee], g_vel[(size_t)Bb*EXTm*Ee];

// ---------------- helpers ----------------
__device__ __forceinline__ u32 smem_u32(const void* p){
    u32 a; asm("{ .reg .u64 t; cvta.to.shared.u64 t, %1; cvt.u32.u64 %0, t; }" : "=r"(a) : "l"(p)); return a;
}
__device__ __forceinline__ void cpasync16(u32 dst, const void* src){
    asm volatile("cp.async.ca.shared.global [%0], [%1], 16;" :: "r"(dst), "l"(src) : "memory");
}
__device__ __forceinline__ void ldsm4(u32 r[4], u32 addr){
    asm volatile("ldmatrix.sync.aligned.m8n8.x4.shared.b16 {%0,%1,%2,%3}, [%4];"
                 : "=r"(r[0]), "=r"(r[1]), "=r"(r[2]), "=r"(r[3]) : "r"(addr));
}
__device__ __forceinline__ void ldsm2(u32 r[2], u32 addr){
    asm volatile("ldmatrix.sync.aligned.m8n8.x2.shared.b16 {%0,%1}, [%2];"
                 : "=r"(r[0]), "=r"(r[1]) : "r"(addr));
}
__device__ __forceinline__ void ldsm2t(u32 r[2], u32 addr){
    asm volatile("ldmatrix.sync.aligned.m8n8.x2.trans.shared.b16 {%0,%1}, [%2];"
                 : "=r"(r[0]), "=r"(r[1]) : "r"(addr));
}
__device__ __forceinline__ void mma16816(float c[4], const u32 a[4], u32 b0, u32 b1){
    asm volatile("mma.sync.aligned.m16n8k16.row.col.f32.bf16.bf16.f32 "
                 "{%0,%1,%2,%3}, {%4,%5,%6,%7}, {%8,%9}, {%0,%1,%2,%3};"
                 : "+f"(c[0]), "+f"(c[1]), "+f"(c[2]), "+f"(c[3])
                 : "r"(a[0]), "r"(a[1]), "r"(a[2]), "r"(a[3]), "r"(b0), "r"(b1));
}
__device__ __forceinline__ void st_hilo(__nv_bfloat16* dh, __nv_bfloat16* dl, size_t off, float2 v){
    __nv_bfloat16 h0 = __float2bfloat16(v.x), h1 = __float2bfloat16(v.y);
    __nv_bfloat16 l0 = __float2bfloat16(v.x - __bfloat162float(h0));
    __nv_bfloat16 l1 = __float2bfloat16(v.y - __bfloat162float(h1));
    *(__nv_bfloat162*)&dh[off] = __halves2bfloat162(h0, h1);
    *(__nv_bfloat162*)&dl[off] = __halves2bfloat162(l0, l1);
}

__device__ __forceinline__ void split_store(size_t off, float4 v,
                                            __nv_bfloat16* dh, __nv_bfloat16* dl){
    st_hilo(dh, dl, off,   make_float2(v.x, v.y));
    st_hilo(dh, dl, off+2, make_float2(v.z, v.w));
}

// ---------------- merged prep ----------------
__global__ void __launch_bounds__(256) prep_kernel(
    const float* __restrict__ x,
    const float* __restrict__ pos, const float* __restrict__ epos,
    const unsigned char* __restrict__ pmask, const unsigned char* __restrict__ emask,
    const float* __restrict__ Wq, const float* __restrict__ Wk,
    const float* __restrict__ Wv, const float* __restrict__ Wve,
    const float* __restrict__ Woe, const float* __restrict__ Wo)
{
    int blk = blockIdx.x;
    if (blk < 6144) {
        int w = blk >> 10, bx = blk & 1023;
        const float* W = (w==0)?Wq:(w==1)?Wk:(w==2)?Wv:(w==3)?Wve:(w==4)?Woe:Wo;
        size_t i = ((size_t)bx*256 + threadIdx.x)*4;
        float4 v = *(const float4*)(W + i);
        split_store((size_t)w*Ee*Ee + i, v, g_wh, g_wl);
    } else if (blk < 8192) {
        int r = blk - 6144;
        int b = r >> 8, n = r & 255;
        int e = threadIdx.x * 4;
        float4 v = *(const float4*)(x + ((size_t)n*Bb + b)*Ee + e);
        split_store((size_t)r*Ee + e, v, g_ah, g_al);
    } else {
        int bn = blk - 8192;
        int b = bn >> 8, n = bn & 255;
        const float* pq = pos + (size_t)(b*Nn + n)*3;
        float px = pq[0], py = pq[1], pz = pq[2];
        unsigned int qm = pmask[b*Nn + n];
        for (int m = threadIdx.x; m < EXTm; m += 256) {
            float ax, ay, az; unsigned int km;
            if (m < Nn) {
                const float* pp = pos + (size_t)(b*Nn + m)*3;
                ax = pp[0]; ay = pp[1]; az = pp[2];
                km = pmask[b*Nn + m];
            } else {
                const float* pp = epos + (size_t)(b*Mm + m - Nn)*3;
                ax = pp[0]; ay = pp[1]; az = pp[2];
                km = emask[b*Mm + m - Nn];
            }
            float dx = px - ax, dy = py - ay, dz = pz - az;
            float dist = sqrtf(dx*dx + dy*dy + dz*dz);
            if (qm | km) dist = 1e6f;
            float f = 1.f / (dist + 1.f);
            if (qm) f = 0.f;
            g_pd[(size_t)bn*EXTm + m] = make_float4(dx*f, dy*f, dz*f, 0.f);
        }
    }
}

// ========== bf16-split mma.sync GEMM (1 sync per K-chunk) ==========
#define ST_ROW   40
#define MAT_SZ   (128*ST_ROW*2)
#define STAGE_SZ (4*MAT_SZ)
#define MM_SMEM  (2*STAGE_SZ)

__global__ void __launch_bounds__(256) mm_mma(float* __restrict__ Cout, int mode)
{
    extern __shared__ __align__(16) char smraw[];
    const u32 smBase = smem_u32(smraw);
    const int t = threadIdx.x, wid = t >> 5, lid = t & 31;
    const int wm = wid >> 2, wn = wid & 3;
    const int col0 = blockIdx.x * 128;
    int unit, row0, arow0;
    if (mode == 0) { unit = blockIdx.z; row0 = blockIdx.y*128; arow0 = row0; }
    else {
        int yy = blockIdx.y;
        if (yy < 16) { unit = 4; row0 = yy*128; arow0 = row0; }
        else         { unit = 5; row0 = (yy-16)*128; arow0 = 2048 + row0; }
    }

    const __nv_bfloat16* srcs[4] = {
        g_ah + (size_t)arow0*Ee,
        g_al + (size_t)arow0*Ee,
        g_wh + (size_t)unit*Ee*Ee + (size_t)col0*Ee,
        g_wl + (size_t)unit*Ee*Ee + (size_t)col0*Ee
    };

    float acc[4][4][4];
#pragma unroll
    for (int i = 0; i < 4; i++)
#pragma unroll
        for (int j = 0; j < 4; j++)
#pragma unroll
            for (int q = 0; q < 4; q++) acc[i][j][q] = 0.f;

    int cp_mat[8], cp_row[8], cp_q[8];
#pragma unroll
    for (int jj = 0; jj < 8; jj++) {
        int id = t + jj*256;
        cp_mat[jj] = id >> 9; int rem = id & 511;
        cp_row[jj] = rem >> 2; cp_q[jj] = rem & 3;
    }

#define ISSUE(kc, stage)                                                          \
    {   int k0 = (kc)*32;                                                         \
        u32 dB = smBase + (stage)*STAGE_SZ;                                       \
        _Pragma("unroll")                                                         \
        for (int jj = 0; jj < 8; jj++) {                                          \
            const __nv_bfloat16* s = srcs[cp_mat[jj]] + (size_t)cp_row[jj]*Ee + k0 + cp_q[jj]*8; \
            cpasync16(dB + cp_mat[jj]*MAT_SZ + cp_row[jj]*(ST_ROW*2) + cp_q[jj]*16, s); \
        }                                                                         \
        asm volatile("cp.async.commit_group;" ::: "memory");                      \
    }

    ISSUE(0, 0);

    const u32 aoff = (u32)(((lid >> 3) & 1) * 8 + (lid & 7));
    const u32 kbl  = (u32)(((lid >> 4) & 1) * 16);

    for (int kc = 0; kc < 32; kc++) {
        int stage = kc & 1;
        asm volatile("cp.async.wait_group 0;" ::: "memory");
        __syncthreads();
        if (kc < 31) ISSUE(kc + 1, stage ^ 1);

        u32 base = smBase + stage*STAGE_SZ;
#pragma unroll
        for (int ks = 0; ks < 2; ks++) {
            u32 kb = kbl + ks*32;
            u32 ah[4][4], al[4][4];
            u32 bh0[4], bh1[4], bl0[4], bl1[4];
#pragma unroll
            for (int im = 0; im < 4; im++) {
                u32 row = (u32)(wm*64 + im*16) + aoff;
                ldsm4(ah[im], base + 0*MAT_SZ + row*(ST_ROW*2) + kb);
                ldsm4(al[im], base + 1*MAT_SZ + row*(ST_ROW*2) + kb);
            }
#pragma unroll
            for (int jn = 0; jn < 2; jn++) {
                u32 row = (u32)(wn*32 + jn*16) + aoff;
                u32 rh[4], rl[4];
                ldsm4(rh, base + 2*MAT_SZ + row*(ST_ROW*2) + kb);
                ldsm4(rl, base + 3*MAT_SZ + row*(ST_ROW*2) + kb);
                bh0[jn*2] = rh[0]; bh1[jn*2] = rh[2]; bh0[jn*2+1] = rh[1]; bh1[jn*2+1] = rh[3];
                bl0[jn*2] = rl[0]; bl1[jn*2] = rl[2]; bl0[jn*2+1] = rl[1]; bl1[jn*2+1] = rl[3];
            }
#pragma unroll
            for (int im = 0; im < 4; im++)
#pragma unroll
                for (int n8 = 0; n8 < 4; n8++) {
                    mma16816(acc[im][n8], ah[im], bh0[n8], bh1[n8]);
                    mma16816(acc[im][n8], al[im], bh0[n8], bh1[n8]);
                    mma16816(acc[im][n8], ah[im], bl0[n8], bl1[n8]);
                }
        }
    }

    const int gid = lid >> 2, tig = lid & 3;
    float* dst5 = (unit == 4) ? Cout : Cout + (size_t)2048*Ee;
#pragma unroll
    for (int im = 0; im < 4; im++) {
#pragma unroll
        for (int n8 = 0; n8 < 4; n8++) {
            int c = col0 + wn*32 + n8*8 + tig*2;
            int r0 = row0 + wm*64 + im*16 + gid;
            int r1 = r0 + 8;
            float2 v0 = make_float2(acc[im][n8][0], acc[im][n8][1]);
            float2 v1 = make_float2(acc[im][n8][2], acc[im][n8][3]);
            if (unit == 0) {
                v0.x *= SCALING; v0.y *= SCALING; v1.x *= SCALING; v1.y *= SCALING;
                st_hilo(g_qh, g_ql, (size_t)r0*Ee + c, v0);
                st_hilo(g_qh, g_ql, (size_t)r1*Ee + c, v1);
            } else if (unit < 4) {
                __nv_bfloat16 *dh, *dl;
                if (unit == 1) { dh = g_kh; dl = g_kl; }
                else if (unit == 2) { dh = g_vh; dl = g_vl; }
                else { dh = g_veh; dl = g_vel; }
                st_hilo(dh, dl, ((size_t)(r0 >> 8)*EXTm + (r0 & 255))*Ee + c, v0);
                st_hilo(dh, dl, ((size_t)(r1 >> 8)*EXTm + (r1 & 255))*Ee + c, v1);
            } else {
                *(float2*)&dst5[(size_t)r0*Ee + c] = v0;
                *(float2*)&dst5[(size_t)r1*Ee + c] = v1;
            }
        }
    }
}

// ---------------- gather ----------------
__global__ void __launch_bounds__(256) gather_kernel(const int* __restrict__ idx)
{
    int bm = blockIdx.x;
    int b = bm >> 9, m = bm & 511;
    int s = idx[bm];
    size_t so = ((size_t)b*EXTm + s)      * Ee;
    size_t dd = ((size_t)b*EXTm + Nn + m) * Ee;
    int e = threadIdx.x * 4;
    *(uint2*)&g_kh [dd+e] = *(const uint2*)&g_kh [so+e];
    *(uint2*)&g_kl [dd+e] = *(const uint2*)&g_kl [so+e];
    *(uint2*)&g_vh [dd+e] = *(const uint2*)&g_vh [so+e];
    *(uint2*)&g_vl [dd+e] = *(const uint2*)&g_vl [so+e];
    *(uint2*)&g_veh[dd+e] = *(const uint2*)&g_veh[so+e];
    *(uint2*)&g_vel[dd+e] = *(const uint2*)&g_vel[so+e];
}

// ================= tensor-core attention =================
#define TQ 32
#define SPITCH 776
#define oS   0
#define oW   99328
#define oQ2  99328
#define oK3  104448
#define oB3  135168
#define oV   173056
#define oPN  214016
#define oMF  214144
#define oSI  217216             // softmax inv[32] (128 B)
#define ATTN_SMEM 217344

__global__ void __launch_bounds__(512, 1) attn_mma(
    const float* __restrict__ bias,
    const unsigned char* __restrict__ pmask, const unsigned char* __restrict__ emask)
{
    extern __shared__ __align__(16) char sm[];
    float* S = (float*)(sm + oS);
    float* qmn = (float*)(sm + oPN);
    float* maskf = (float*)(sm + oMF);
    float* sinv = (float*)(sm + oSI);
    const u32 smb = smem_u32(sm);

    const int t = threadIdx.x, w = t >> 5, lid = t & 31;
    const int nt = blockIdx.x, h = blockIdx.y, b = blockIdx.z;
    const int n0 = nt * TQ;

    const float* biasrow = bias + ((u64)(b*Hh + h)*Nn + n0)*EXTm;

#define ISSUE_V(mt, s)                                                                      \
    {   _Pragma("unroll")                                                                   \
        for (int jj = 0; jj < 2; jj++) {                                                    \
            int id = t + jj*512;                                                            \
            int arr = id >> 8, u = id & 255;                                                \
            int row = u >> 2, q = u & 3;                                                    \
            const __nv_bfloat16* src = ((arr==0)?g_vh:(arr==1)?g_vl:(arr==2)?g_veh:g_vel)   \
                + ((u64)(b*EXTm + (mt)*64 + row))*Ee + h*32 + q*8;                          \
            cpasync16(smb + oV + (s)*20480 + arr*5120 + row*80 + q*16, src);                \
        }                                                                                   \
        asm volatile("cp.async.commit_group;" ::: "memory");                                \
    }

    const int ka_arr = t >> 8, ka_u = t & 255;
    const int ka_row = ka_u >> 2, ka_q = ka_u & 3;
    const int bb_row = t >> 4, bb_q = t & 15;
#define ISSUE_A(mt, s)                                                                     \
    {   const __nv_bfloat16* ksrc = (ka_arr ? g_kl : g_kh)                                 \
            + ((u64)(b*EXTm + (mt)*64 + ka_row))*Ee + h*32 + ka_q*8;                       \
        cpasync16(smb + oK3 + (s)*10240 + ka_arr*5120 + ka_row*80 + ka_q*16, ksrc);        \
        const float* bsrc = biasrow + (u64)bb_row*EXTm + (mt)*64 + bb_q*4;                 \
        cpasync16(smb + oB3 + (s)*8192 + bb_row*256 + bb_q*16, bsrc);                      \
        asm volatile("cp.async.commit_group;" ::: "memory");                               \
    }

    ISSUE_V(0, 0);
    ISSUE_A(0, 0);
    ISSUE_A(1, 1);

    // ---- init staging ----
    if (t < 256) {
        int r = t >> 3, q = t & 7;
        u64 gi = ((u64)(b*Nn + n0 + r))*Ee + h*32 + q*4;
        *(uint2*)(sm + oQ2 + r*80 + q*8)        = *(const uint2*)(g_qh + gi);
        *(uint2*)(sm + oQ2 + 2560 + r*80 + q*8) = *(const uint2*)(g_ql + gi);
    }
    if (t < 32) qmn[t] = pmask[b*Nn + n0 + t] ? 1.f : 0.f;
    for (int i = t; i < EXTm; i += 512) {
        unsigned int mq = (i < Nn) ? pmask[b*Nn + i] : emask[b*Mm + i - Nn];
        maskf[i] = mq ? 1.f : 0.f;
    }
    __syncthreads();

    const u32 aoff = (u32)(((lid >> 3) & 1) * 8 + (lid & 7));
    const u32 acol = (u32)(((lid >> 4) & 1) * 16);

    // ---- phase A: S = Q K^T + bias, masked; 3-stage, 1 sync/tile ----
    {
        const int wn = w >> 3, wm8 = w & 7;
        u32 qah[2][4], qal[2][4];
#pragma unroll
        for (int ks = 0; ks < 2; ks++) {
            u32 qa = smb + oQ2 + (wn*16 + aoff)*80 + acol + ks*32;
            ldsm4(qah[ks], qa); ldsm4(qal[ks], qa + 2560);
        }
        for (int mt = 0; mt < 12; mt++) {
            int s = mt % 3;
            if (mt < 10) asm volatile("cp.async.wait_group 1;" ::: "memory");
            else         asm volatile("cp.async.wait_group 0;" ::: "memory");
            __syncthreads();
            if (mt < 10) ISSUE_A(mt + 2, (mt + 2) % 3);
            float c[4] = {0.f, 0.f, 0.f, 0.f};
            u32 kbase = smb + oK3 + s*10240;
#pragma unroll
            for (int ks = 0; ks < 2; ks++) {
                u32 ka = kbase + (wm8*8 + (lid & 7))*80 + ((lid >> 3) & 1)*16 + ks*32;
                u32 bh[2], bl[2];
                ldsm2(bh, ka); ldsm2(bl, ka + 5120);
                mma16816(c, qah[ks], bh[0], bh[1]);
                mma16816(c, qal[ks], bh[0], bh[1]);
                mma16816(c, qah[ks], bl[0], bl[1]);
            }
            int row = wn*16 + (lid >> 2);
            int colL = wm8*8 + (lid & 3)*2;
            int col = mt*64 + colL;
            float* btile = (float*)(sm + oB3 + s*8192);
            float2 b0 = *(float2*)&btile[row*64 + colL];
            float2 b1 = *(float2*)&btile[(row+8)*64 + colL];
            float qm0 = qmn[row], qm1 = qmn[row+8];
            float m0 = maskf[col], m1 = maskf[col+1];
            c[0] = (qm0 + m0 > 0.f) ? NEGINF : c[0] + b0.x;
            c[1] = (qm0 + m1 > 0.f) ? NEGINF : c[1] + b0.y;
            c[2] = (qm1 + m0 > 0.f) ? NEGINF : c[2] + b1.x;
            c[3] = (qm1 + m1 > 0.f) ? NEGINF : c[3] + b1.y;
            *(float2*)&S[row*SPITCH + col]     = make_float2(c[0], c[1]);
            *(float2*)&S[(row+8)*SPITCH + col] = make_float2(c[2], c[3]);
        }
    }
    __syncthreads();

    // ---- softmax: store UNNORMALIZED exp; row inv -> sinv ----
#pragma unroll
    for (int rr = 0; rr < 2; rr++) {
        int ni = w*2 + rr;
        float lm = NEGINF;
#pragma unroll
        for (int i = 0; i < 24; i++) lm = fmaxf(lm, S[ni*SPITCH + lid + i*32]);
#pragma unroll
        for (int o = 16; o; o >>= 1) lm = fmaxf(lm, __shfl_xor_sync(0xffffffffu, lm, o));
        float ls = 0.f;
#pragma unroll
        for (int i = 0; i < 24; i++) {
            float p = __expf(S[ni*SPITCH + lid + i*32] - lm);
            S[ni*SPITCH + lid + i*32] = p;
            ls += p;
        }
#pragma unroll
        for (int o = 16; o; o >>= 1) ls += __shfl_xor_sync(0xffffffffu, ls, o);
        if (lid == 0) sinv[ni] = 1.f / ls;
    }
    __syncthreads();

    // ---- phase B: warps 0-7 = vec (ch1-3, all fd, 1 ks); warps 8-15 = xo ----
    const int isVec = (w < 8);
    const int w8 = w & 7;
    const int fn  = w8 & 1;
    const int ksq = w8 >> 1;               // 0..3
    float acc[3][4][4];
#pragma unroll
    for (int c = 0; c < 3; c++)
#pragma unroll
        for (int fd = 0; fd < 4; fd++)
#pragma unroll
            for (int q = 0; q < 4; q++) acc[c][fd][q] = 0.f;

    const float4* pdg = g_pd + (u64)(b*Nn + n0)*EXTm;
    const int pd_ni0 = t >> 5,          pd_ml0 = (t & 31)*2;
    const int pd_ni1 = (t + 512) >> 5,  pd_ml1 = ((t + 512) & 31)*2;

    for (int mt = 0; mt < 12; mt++) {
        int s = mt & 1;
        u32 wst = (u32)(oW + s*36864);
        // weight build into W[s]; p normalized here via sinv
#pragma unroll
        for (int jj = 0; jj < 2; jj++) {
            int ni = jj ? pd_ni1 : pd_ni0;
            int ml = jj ? pd_ml1 : pd_ml0;
            float4 d0 = pdg[(u64)ni*EXTm + mt*64 + ml];
            float4 d1 = pdg[(u64)ni*EXTm + mt*64 + ml + 1];
            float inv = sinv[ni];
            float2 pp = *(float2*)&S[ni*SPITCH + mt*64 + ml];
            pp.x *= inv; pp.y *= inv;
            float wsa[4] = { pp.x, pp.x*d0.x, pp.x*d0.y, pp.x*d0.z };
            float wsb[4] = { pp.y, pp.y*d1.x, pp.y*d1.y, pp.y*d1.z };
#pragma unroll
            for (int c = 0; c < 4; c++) {
                __nv_bfloat16 ha = __float2bfloat16(wsa[c]);
                __nv_bfloat16 hb = __float2bfloat16(wsb[c]);
                __nv_bfloat16 la = __float2bfloat16(wsa[c] - __bfloat162float(ha));
                __nv_bfloat16 lb = __float2bfloat16(wsb[c] - __bfloat162float(hb));
                *(__nv_bfloat162*)(sm + wst + c*4608 + ni*144 + ml*2)         = __halves2bfloat162(ha, hb);
                *(__nv_bfloat162*)(sm + wst + 18432 + c*4608 + ni*144 + ml*2) = __halves2bfloat162(la, lb);
            }
        }
        asm volatile("cp.async.wait_group 0;" ::: "memory");
        __syncthreads();
        if (mt < 11) ISSUE_V(mt + 1, s ^ 1);
        u32 vbase = smb + oV + s*20480;
        u32 vrow = (u32)(ksq*16 + (lid & 15));
        if (isVec) {
            u32 ah[3][4], al[3][4];
#pragma unroll
            for (int c = 0; c < 3; c++) {
                u32 wa = wst + (c+1)*4608 + (fn*16 + aoff)*144 + acol + ksq*32;
                ldsm4(ah[c], smb + wa); ldsm4(al[c], smb + wa + 18432);
            }
#pragma unroll
            for (int fd = 0; fd < 4; fd++) {
                u32 va = vbase + vrow*80 + fd*16;       // varr = 0 (V)
                u32 bh[2], bl[2];
                ldsm2t(bh, va);
                ldsm2t(bl, va + 5120);
#pragma unroll
                for (int c = 0; c < 3; c++) {
                    mma16816(acc[c][fd], ah[c], bh[0], bh[1]);
                    mma16816(acc[c][fd], al[c], bh[0], bh[1]);
                    mma16816(acc[c][fd], ah[c], bl[0], bl[1]);
                }
            }
        } else {
            u32 ah0[4], al0[4];
            u32 wa = wst + 0*4608 + (fn*16 + aoff)*144 + acol + ksq*32;
            ldsm4(ah0, smb + wa); ldsm4(al0, smb + wa + 18432);
#pragma unroll
            for (int fd = 0; fd < 4; fd++) {
                u32 va = vbase + 2u*5120 + vrow*80 + fd*16;   // varr = 2 (VE)
                u32 bh[2], bl[2];
                ldsm2t(bh, va);
                ldsm2t(bl, va + 5120);
                mma16816(acc[0][fd], ah0, bh[0], bh[1]);
                mma16816(acc[0][fd], al0, bh[0], bh[1]);
                mma16816(acc[0][fd], ah0, bl[0], bl[1]);
            }
        }
    }

    // ---- cross-ksq reduction (2 pairwise rounds) via scratch at oS ----
    __syncthreads();
    float4* red = (float4*)(sm + oS);     // [bank2][slot32][lid32] float4
    // slot: vec -> (fn*3 + c)*4 + fd  (0..23); xo -> 24 + fn*4 + fd
    const int nCh = isVec ? 3 : 1;
    const int slot0 = isVec ? (fn*3*4) : (24 + fn*4);
    if (ksq & 1) {                         // ksq 1,3 write bank (ksq>>1)
        int bank = ksq >> 1;
#pragma unroll
        for (int c = 0; c < 3; c++) {
            if (c >= nCh) break;
#pragma unroll
            for (int fd = 0; fd < 4; fd++)
                red[(bank*32 + slot0 + c*4 + fd)*32 + lid] =
                    make_float4(acc[c][fd][0], acc[c][fd][1], acc[c][fd][2], acc[c][fd][3]);
        }
    }
    __syncthreads();
    if (!(ksq & 1)) {                      // ksq 0,2 add bank (ksq>>1)
        int bank = ksq >> 1;
#pragma unroll
        for (int c = 0; c < 3; c++) {
            if (c >= nCh) break;
#pragma unroll
            for (int fd = 0; fd < 4; fd++) {
                float4 o = red[(bank*32 + slot0 + c*4 + fd)*32 + lid];
                acc[c][fd][0] += o.x; acc[c][fd][1] += o.y;
                acc[c][fd][2] += o.z; acc[c][fd][3] += o.w;
            }
        }
    }
    __syncthreads();
    if (ksq == 2) {                        // write bank 0
#pragma unroll
        for (int c = 0; c < 3; c++) {
            if (c >= nCh) break;
#pragma unroll
            for (int fd = 0; fd < 4; fd++)
                red[(slot0 + c*4 + fd)*32 + lid] =
                    make_float4(acc[c][fd][0], acc[c][fd][1], acc[c][fd][2], acc[c][fd][3]);
        }
    }
    __syncthreads();
    if (ksq == 0) {
        int gid = lid >> 2, tig = lid & 3;
#pragma unroll
        for (int c = 0; c < 3; c++) {
            if (c >= nCh) break;
#pragma unroll
            for (int fd = 0; fd < 4; fd++) {
                float4 o = red[(slot0 + c*4 + fd)*32 + lid];
                float2 v0 = make_float2(acc[c][fd][0] + o.x, acc[c][fd][1] + o.y);
                float2 v1 = make_float2(acc[c][fd][2] + o.z, acc[c][fd][3] + o.w);
                int ch = isVec ? (c + 1) : 0;
                int col = h*32 + fd*8 + tig*2;
                int r0 = n0 + fn*16 + gid;
                int r1 = r0 + 8;
                u64 row0g, row1g;
                if (ch == 0) {
                    row0g = (u64)(b*Nn + r0);
                    row1g = (u64)(b*Nn + r1);
                } else {
                    row0g = 2048 + ((u64)(b*Nn + r0)*3 + (ch-1));
                    row1g = 2048 + ((u64)(b*Nn + r1)*3 + (ch-1));
                }
                st_hilo(g_ah, g_al, row0g*Ee + col, v0);
                st_hilo(g_ah, g_al, row1g*Ee + col, v1);
            }
        }
    }
}

// ---------------- host entry ----------------
extern "C" void kernel_launch(void* const* d_in, const int* in_sizes, int n_in,
                              void* d_out, int out_size)
{
    const float* x    = (const float*)d_in[0];
    const float* pos  = (const float*)d_in[1];
    const float* epos = (const float*)d_in[2];
    const float* bias = (const float*)d_in[3];
    const unsigned char* pmask = (const unsigned char*)d_in[4];
    const unsigned char* emask = (const unsigned char*)d_in[5];
    const int*   idx  = (const int*)d_in[6];
    const float* Wq   = (const float*)d_in[7];
    const float* Wk   = (const float*)d_in[8];
    const float* Wv   = (const float*)d_in[9];
    const float* Wve  = (const float*)d_in[10];
    const float* Wo   = (const float*)d_in[11];
    const float* Woe  = (const float*)d_in[12];
    float* out = (float*)d_out;

    cudaFuncSetAttribute(mm_mma, cudaFuncAttributeMaxDynamicSharedMemorySize, MM_SMEM);
    cudaFuncSetAttribute(attn_mma, cudaFuncAttributeMaxDynamicSharedMemorySize, ATTN_SMEM);

    prep_kernel<<<10240, 256>>>(x, pos, epos, pmask, emask, Wq, Wk, Wv, Wve, Woe, Wo);

    mm_mma<<<dim3(8, 16, 4), 256, MM_SMEM>>>(nullptr, 0);    // q,k,v,ve projections

    gather_kernel<<<Bb*Mm, 256>>>(idx);

    attn_mma<<<dim3(8, 32, 8), 512, ATTN_SMEM>>>(bias, pmask, emask);

    mm_mma<<<dim3(8, 64, 1), 256, MM_SMEM>>>(out, 6);        // merged xo@Woe + vec@Wo
}

// round 15
// speedup vs baseline: 1.4504x; 1.4504x over previous
#include <cuda_runtime.h>
#include <cuda_bf16.h>
#include <cstdint>
#include <cstddef>

typedef unsigned int u32;
typedef unsigned long long u64;

#define Bb   8
#define Nn   256
#define Mm   512
#define EXTm 768
#define Ee   1024
#define Hh   32
#define SCALING 0.17677669529663687f
#define NEGINF  -3.402823466e38f

// ---------------- scratch ----------------
__device__ float4 g_pd[(size_t)Bb*Nn*EXTm];
__device__ __nv_bfloat16 g_ah[(size_t)8192*Ee];
__device__ __nv_bfloat16 g_al[(size_t)8192*Ee];
__device__ __nv_bfloat16 g_wh[(size_t)6*Ee*Ee];
__device__ __nv_bfloat16 g_wl[(size_t)6*Ee*Ee];
__device__ __nv_bfloat16 g_qh[(size_t)Bb*Nn*Ee],  g_ql[(size_t)Bb*Nn*Ee];
__device__ __nv_bfloat16 g_kh[(size_t)Bb*EXTm*Ee], g_kl[(size_t)Bb*EXTm*Ee];
__device__ __nv_bfloat16 g_vh[(size_t)Bb*EXTm*Ee], g_vl[(size_t)Bb*EXTm*Ee];
__device__ __nv_bfloat16 g_veh[(size_t)Bb*EXTm*Ee], g_vel[(size_t)Bb*EXTm*Ee];

// ---------------- helpers ----------------
__device__ __forceinline__ u32 smem_u32(const void* p){
    u32 a; asm("{ .reg .u64 t; cvta.to.shared.u64 t, %1; cvt.u32.u64 %0, t; }" : "=r"(a) : "l"(p)); return a;
}
__device__ __forceinline__ void cpasync16(u32 dst, const void* src){
    asm volatile("cp.async.ca.shared.global [%0], [%1], 16;" :: "r"(dst), "l"(src) : "memory");
}
__device__ __forceinline__ void ldsm4(u32 r[4], u32 addr){
    asm volatile("ldmatrix.sync.aligned.m8n8.x4.shared.b16 {%0,%1,%2,%3}, [%4];"
                 : "=r"(r[0]), "=r"(r[1]), "=r"(r[2]), "=r"(r[3]) : "r"(addr));
}
__device__ __forceinline__ void ldsm2(u32 r[2], u32 addr){
    asm volatile("ldmatrix.sync.aligned.m8n8.x2.shared.b16 {%0,%1}, [%2];"
                 : "=r"(r[0]), "=r"(r[1]) : "r"(addr));
}
__device__ __forceinline__ void ldsm2t(u32 r[2], u32 addr){
    asm volatile("ldmatrix.sync.aligned.m8n8.x2.trans.shared.b16 {%0,%1}, [%2];"
                 : "=r"(r[0]), "=r"(r[1]) : "r"(addr));
}
__device__ __forceinline__ void mma16816(float c[4], const u32 a[4], u32 b0, u32 b1){
    asm volatile("mma.sync.aligned.m16n8k16.row.col.f32.bf16.bf16.f32 "
                 "{%0,%1,%2,%3}, {%4,%5,%6,%7}, {%8,%9}, {%0,%1,%2,%3};"
                 : "+f"(c[0]), "+f"(c[1]), "+f"(c[2]), "+f"(c[3])
                 : "r"(a[0]), "r"(a[1]), "r"(a[2]), "r"(a[3]), "r"(b0), "r"(b1));
}
__device__ __forceinline__ void st_hilo(__nv_bfloat16* dh, __nv_bfloat16* dl, size_t off, float2 v){
    __nv_bfloat16 h0 = __float2bfloat16(v.x), h1 = __float2bfloat16(v.y);
    __nv_bfloat16 l0 = __float2bfloat16(v.x - __bfloat162float(h0));
    __nv_bfloat16 l1 = __float2bfloat16(v.y - __bfloat162float(h1));
    *(__nv_bfloat162*)&dh[off] = __halves2bfloat162(h0, h1);
    *(__nv_bfloat162*)&dl[off] = __halves2bfloat162(l0, l1);
}

__device__ __forceinline__ void split_store(size_t off, float4 v,
                                            __nv_bfloat16* dh, __nv_bfloat16* dl){
    st_hilo(dh, dl, off,   make_float2(v.x, v.y));
    st_hilo(dh, dl, off+2, make_float2(v.z, v.w));
}

// ---------------- merged prep ----------------
__global__ void __launch_bounds__(256) prep_kernel(
    const float* __restrict__ x,
    const float* __restrict__ pos, const float* __restrict__ epos,
    const unsigned char* __restrict__ pmask, const unsigned char* __restrict__ emask,
    const float* __restrict__ Wq, const float* __restrict__ Wk,
    const float* __restrict__ Wv, const float* __restrict__ Wve,
    const float* __restrict__ Woe, const float* __restrict__ Wo)
{
    int blk = blockIdx.x;
    if (blk < 6144) {
        int w = blk >> 10, bx = blk & 1023;
        const float* W = (w==0)?Wq:(w==1)?Wk:(w==2)?Wv:(w==3)?Wve:(w==4)?Woe:Wo;
        size_t i = ((size_t)bx*256 + threadIdx.x)*4;
        float4 v = *(const float4*)(W + i);
        split_store((size_t)w*Ee*Ee + i, v, g_wh, g_wl);
    } else if (blk < 8192) {
        int r = blk - 6144;
        int b = r >> 8, n = r & 255;
        int e = threadIdx.x * 4;
        float4 v = *(const float4*)(x + ((size_t)n*Bb + b)*Ee + e);
        split_store((size_t)r*Ee + e, v, g_ah, g_al);
    } else {
        int bn = blk - 8192;
        int b = bn >> 8, n = bn & 255;
        const float* pq = pos + (size_t)(b*Nn + n)*3;
        float px = pq[0], py = pq[1], pz = pq[2];
        unsigned int qm = pmask[b*Nn + n];
        for (int m = threadIdx.x; m < EXTm; m += 256) {
            float ax, ay, az; unsigned int km;
            if (m < Nn) {
                const float* pp = pos + (size_t)(b*Nn + m)*3;
                ax = pp[0]; ay = pp[1]; az = pp[2];
                km = pmask[b*Nn + m];
            } else {
                const float* pp = epos + (size_t)(b*Mm + m - Nn)*3;
                ax = pp[0]; ay = pp[1]; az = pp[2];
                km = emask[b*Mm + m - Nn];
            }
            float dx = px - ax, dy = py - ay, dz = pz - az;
            float dist = sqrtf(dx*dx + dy*dy + dz*dz);
            if (qm | km) dist = 1e6f;
            float f = 1.f / (dist + 1.f);
            if (qm) f = 0.f;
            g_pd[(size_t)bn*EXTm + m] = make_float4(dx*f, dy*f, dz*f, 0.f);
        }
    }
}

// ========== bf16-split mma.sync GEMM (1 sync per K-chunk) ==========
#define ST_ROW   40
#define MAT_SZ   (128*ST_ROW*2)
#define STAGE_SZ (4*MAT_SZ)
#define MM_SMEM  (2*STAGE_SZ)

__global__ void __launch_bounds__(256) mm_mma(float* __restrict__ Cout, int mode)
{
    extern __shared__ __align__(16) char smraw[];
    const u32 smBase = smem_u32(smraw);
    const int t = threadIdx.x, wid = t >> 5, lid = t & 31;
    const int wm = wid >> 2, wn = wid & 3;
    const int col0 = blockIdx.x * 128;
    int unit, row0, arow0;
    if (mode == 0) { unit = blockIdx.z; row0 = blockIdx.y*128; arow0 = row0; }
    else {
        int yy = blockIdx.y;
        if (yy < 16) { unit = 4; row0 = yy*128; arow0 = row0; }
        else         { unit = 5; row0 = (yy-16)*128; arow0 = 2048 + row0; }
    }

    const __nv_bfloat16* srcs[4] = {
        g_ah + (size_t)arow0*Ee,
        g_al + (size_t)arow0*Ee,
        g_wh + (size_t)unit*Ee*Ee + (size_t)col0*Ee,
        g_wl + (size_t)unit*Ee*Ee + (size_t)col0*Ee
    };

    float acc[4][4][4];
#pragma unroll
    for (int i = 0; i < 4; i++)
#pragma unroll
        for (int j = 0; j < 4; j++)
#pragma unroll
            for (int q = 0; q < 4; q++) acc[i][j][q] = 0.f;

    int cp_mat[8], cp_row[8], cp_q[8];
#pragma unroll
    for (int jj = 0; jj < 8; jj++) {
        int id = t + jj*256;
        cp_mat[jj] = id >> 9; int rem = id & 511;
        cp_row[jj] = rem >> 2; cp_q[jj] = rem & 3;
    }

#define ISSUE(kc, stage)                                                          \
    {   int k0 = (kc)*32;                                                         \
        u32 dB = smBase + (stage)*STAGE_SZ;                                       \
        _Pragma("unroll")                                                         \
        for (int jj = 0; jj < 8; jj++) {                                          \
            const __nv_bfloat16* s = srcs[cp_mat[jj]] + (size_t)cp_row[jj]*Ee + k0 + cp_q[jj]*8; \
            cpasync16(dB + cp_mat[jj]*MAT_SZ + cp_row[jj]*(ST_ROW*2) + cp_q[jj]*16, s); \
        }                                                                         \
        asm volatile("cp.async.commit_group;" ::: "memory");                      \
    }

    ISSUE(0, 0);

    const u32 aoff = (u32)(((lid >> 3) & 1) * 8 + (lid & 7));
    const u32 kbl  = (u32)(((lid >> 4) & 1) * 16);

    for (int kc = 0; kc < 32; kc++) {
        int stage = kc & 1;
        asm volatile("cp.async.wait_group 0;" ::: "memory");
        __syncthreads();
        if (kc < 31) ISSUE(kc + 1, stage ^ 1);

        u32 base = smBase + stage*STAGE_SZ;
#pragma unroll
        for (int ks = 0; ks < 2; ks++) {
            u32 kb = kbl + ks*32;
            u32 ah[4][4], al[4][4];
            u32 bh0[4], bh1[4], bl0[4], bl1[4];
#pragma unroll
            for (int im = 0; im < 4; im++) {
                u32 row = (u32)(wm*64 + im*16) + aoff;
                ldsm4(ah[im], base + 0*MAT_SZ + row*(ST_ROW*2) + kb);
                ldsm4(al[im], base + 1*MAT_SZ + row*(ST_ROW*2) + kb);
            }
#pragma unroll
            for (int jn = 0; jn < 2; jn++) {
                u32 row = (u32)(wn*32 + jn*16) + aoff;
                u32 rh[4], rl[4];
                ldsm4(rh, base + 2*MAT_SZ + row*(ST_ROW*2) + kb);
                ldsm4(rl, base + 3*MAT_SZ + row*(ST_ROW*2) + kb);
                bh0[jn*2] = rh[0]; bh1[jn*2] = rh[2]; bh0[jn*2+1] = rh[1]; bh1[jn*2+1] = rh[3];
                bl0[jn*2] = rl[0]; bl1[jn*2] = rl[2]; bl0[jn*2+1] = rl[1]; bl1[jn*2+1] = rl[3];
            }
#pragma unroll
            for (int im = 0; im < 4; im++)
#pragma unroll
                for (int n8 = 0; n8 < 4; n8++) {
                    mma16816(acc[im][n8], ah[im], bh0[n8], bh1[n8]);
                    mma16816(acc[im][n8], al[im], bh0[n8], bh1[n8]);
                    mma16816(acc[im][n8], ah[im], bl0[n8], bl1[n8]);
                }
        }
    }

    const int gid = lid >> 2, tig = lid & 3;
    float* dst5 = (unit == 4) ? Cout : Cout + (size_t)2048*Ee;
#pragma unroll
    for (int im = 0; im < 4; im++) {
#pragma unroll
        for (int n8 = 0; n8 < 4; n8++) {
            int c = col0 + wn*32 + n8*8 + tig*2;
            int r0 = row0 + wm*64 + im*16 + gid;
            int r1 = r0 + 8;
            float2 v0 = make_float2(acc[im][n8][0], acc[im][n8][1]);
            float2 v1 = make_float2(acc[im][n8][2], acc[im][n8][3]);
            if (unit == 0) {
                v0.x *= SCALING; v0.y *= SCALING; v1.x *= SCALING; v1.y *= SCALING;
                st_hilo(g_qh, g_ql, (size_t)r0*Ee + c, v0);
                st_hilo(g_qh, g_ql, (size_t)r1*Ee + c, v1);
            } else if (unit < 4) {
                __nv_bfloat16 *dh, *dl;
                if (unit == 1) { dh = g_kh; dl = g_kl; }
                else if (unit == 2) { dh = g_vh; dl = g_vl; }
                else { dh = g_veh; dl = g_vel; }
                st_hilo(dh, dl, ((size_t)(r0 >> 8)*EXTm + (r0 & 255))*Ee + c, v0);
                st_hilo(dh, dl, ((size_t)(r1 >> 8)*EXTm + (r1 & 255))*Ee + c, v1);
            } else {
                *(float2*)&dst5[(size_t)r0*Ee + c] = v0;
                *(float2*)&dst5[(size_t)r1*Ee + c] = v1;
            }
        }
    }
}

// ---------------- gather ----------------
__global__ void __launch_bounds__(256) gather_kernel(const int* __restrict__ idx)
{
    int bm = blockIdx.x;
    int b = bm >> 9, m = bm & 511;
    int s = idx[bm];
    size_t so = ((size_t)b*EXTm + s)      * Ee;
    size_t dd = ((size_t)b*EXTm + Nn + m) * Ee;
    int e = threadIdx.x * 4;
    *(uint2*)&g_kh [dd+e] = *(const uint2*)&g_kh [so+e];
    *(uint2*)&g_kl [dd+e] = *(const uint2*)&g_kl [so+e];
    *(uint2*)&g_vh [dd+e] = *(const uint2*)&g_vh [so+e];
    *(uint2*)&g_vl [dd+e] = *(const uint2*)&g_vl [so+e];
    *(uint2*)&g_veh[dd+e] = *(const uint2*)&g_veh[so+e];
    *(uint2*)&g_vel[dd+e] = *(const uint2*)&g_vel[so+e];
}

// ================= tensor-core attention =================
#define TQ 32
#define SPITCH 776
#define oS   0
#define oW   99328
#define oQ2  99328
#define oK3  104448
#define oB3  135168
#define oV   173056
#define oPN  214016
#define oMF  214144
#define oSI  217216             // softmax inv[32] (128 B)
#define ATTN_SMEM 217344

__global__ void __launch_bounds__(512, 1) attn_mma(
    const float* __restrict__ bias,
    const unsigned char* __restrict__ pmask, const unsigned char* __restrict__ emask)
{
    extern __shared__ __align__(16) char sm[];
    float* S = (float*)(sm + oS);
    float* qmn = (float*)(sm + oPN);
    float* maskf = (float*)(sm + oMF);
    float* sinv = (float*)(sm + oSI);
    const u32 smb = smem_u32(sm);

    const int t = threadIdx.x, w = t >> 5, lid = t & 31;
    const int nt = blockIdx.x, h = blockIdx.y, b = blockIdx.z;
    const int n0 = nt * TQ;

    const float* biasrow = bias + ((u64)(b*Hh + h)*Nn + n0)*EXTm;

#define ISSUE_V(mt, s)                                                                      \
    {   _Pragma("unroll")                                                                   \
        for (int jj = 0; jj < 2; jj++) {                                                    \
            int id = t + jj*512;                                                            \
            int arr = id >> 8, u = id & 255;                                                \
            int row = u >> 2, q = u & 3;                                                    \
            const __nv_bfloat16* src = ((arr==0)?g_vh:(arr==1)?g_vl:(arr==2)?g_veh:g_vel)   \
                + ((u64)(b*EXTm + (mt)*64 + row))*Ee + h*32 + q*8;                          \
            cpasync16(smb + oV + (s)*20480 + arr*5120 + row*80 + q*16, src);                \
        }                                                                                   \
        asm volatile("cp.async.commit_group;" ::: "memory");                                \
    }

    const int ka_arr = t >> 8, ka_u = t & 255;
    const int ka_row = ka_u >> 2, ka_q = ka_u & 3;
    const int bb_row = t >> 4, bb_q = t & 15;
#define ISSUE_A(mt, s)                                                                     \
    {   const __nv_bfloat16* ksrc = (ka_arr ? g_kl : g_kh)                                 \
            + ((u64)(b*EXTm + (mt)*64 + ka_row))*Ee + h*32 + ka_q*8;                       \
        cpasync16(smb + oK3 + (s)*10240 + ka_arr*5120 + ka_row*80 + ka_q*16, ksrc);        \
        const float* bsrc = biasrow + (u64)bb_row*EXTm + (mt)*64 + bb_q*4;                 \
        cpasync16(smb + oB3 + (s)*8192 + bb_row*256 + bb_q*16, bsrc);                      \
        asm volatile("cp.async.commit_group;" ::: "memory");                               \
    }

    ISSUE_V(0, 0);
    ISSUE_A(0, 0);
    ISSUE_A(1, 1);

    // ---- init staging ----
    if (t < 256) {
        int r = t >> 3, q = t & 7;
        u64 gi = ((u64)(b*Nn + n0 + r))*Ee + h*32 + q*4;
        *(uint2*)(sm + oQ2 + r*80 + q*8)        = *(const uint2*)(g_qh + gi);
        *(uint2*)(sm + oQ2 + 2560 + r*80 + q*8) = *(const uint2*)(g_ql + gi);
    }
    if (t < 32) qmn[t] = pmask[b*Nn + n0 + t] ? 1.f : 0.f;
    for (int i = t; i < EXTm; i += 512) {
        unsigned int mq = (i < Nn) ? pmask[b*Nn + i] : emask[b*Mm + i - Nn];
        maskf[i] = mq ? 1.f : 0.f;
    }
    __syncthreads();

    const u32 aoff = (u32)(((lid >> 3) & 1) * 8 + (lid & 7));
    const u32 acol = (u32)(((lid >> 4) & 1) * 16);

    // ---- phase A: S = Q K^T + bias, masked; 3-stage, 1 sync/tile ----
    {
        const int wn = w >> 3, wm8 = w & 7;
        u32 qah[2][4], qal[2][4];
#pragma unroll
        for (int ks = 0; ks < 2; ks++) {
            u32 qa = smb + oQ2 + (wn*16 + aoff)*80 + acol + ks*32;
            ldsm4(qah[ks], qa); ldsm4(qal[ks], qa + 2560);
        }
        for (int mt = 0; mt < 12; mt++) {
            int s = mt % 3;
            if (mt < 10) asm volatile("cp.async.wait_group 1;" ::: "memory");
            else         asm volatile("cp.async.wait_group 0;" ::: "memory");
            __syncthreads();
            if (mt < 10) ISSUE_A(mt + 2, (mt + 2) % 3);
            float c[4] = {0.f, 0.f, 0.f, 0.f};
            u32 kbase = smb + oK3 + s*10240;
#pragma unroll
            for (int ks = 0; ks < 2; ks++) {
                u32 ka = kbase + (wm8*8 + (lid & 7))*80 + ((lid >> 3) & 1)*16 + ks*32;
                u32 bh[2], bl[2];
                ldsm2(bh, ka); ldsm2(bl, ka + 5120);
                mma16816(c, qah[ks], bh[0], bh[1]);
                mma16816(c, qal[ks], bh[0], bh[1]);
                mma16816(c, qah[ks], bl[0], bl[1]);
            }
            int row = wn*16 + (lid >> 2);
            int colL = wm8*8 + (lid & 3)*2;
            int col = mt*64 + colL;
            float* btile = (float*)(sm + oB3 + s*8192);
            float2 b0 = *(float2*)&btile[row*64 + colL];
            float2 b1 = *(float2*)&btile[(row+8)*64 + colL];
            float qm0 = qmn[row], qm1 = qmn[row+8];
            float m0 = maskf[col], m1 = maskf[col+1];
            c[0] = (qm0 + m0 > 0.f) ? NEGINF : c[0] + b0.x;
            c[1] = (qm0 + m1 > 0.f) ? NEGINF : c[1] + b0.y;
            c[2] = (qm1 + m0 > 0.f) ? NEGINF : c[2] + b1.x;
            c[3] = (qm1 + m1 > 0.f) ? NEGINF : c[3] + b1.y;
            *(float2*)&S[row*SPITCH + col]     = make_float2(c[0], c[1]);
            *(float2*)&S[(row+8)*SPITCH + col] = make_float2(c[2], c[3]);
        }
    }
    __syncthreads();

    // ---- softmax: store UNNORMALIZED exp; per-row inv -> sinv ----
#pragma unroll
    for (int rr = 0; rr < 2; rr++) {
        int ni = w*2 + rr;
        float lm = NEGINF;
#pragma unroll
        for (int i = 0; i < 24; i++) lm = fmaxf(lm, S[ni*SPITCH + lid + i*32]);
#pragma unroll
        for (int o = 16; o; o >>= 1) lm = fmaxf(lm, __shfl_xor_sync(0xffffffffu, lm, o));
        float ls = 0.f;
#pragma unroll
        for (int i = 0; i < 24; i++) {
            float p = __expf(S[ni*SPITCH + lid + i*32] - lm);
            S[ni*SPITCH + lid + i*32] = p;
            ls += p;
        }
#pragma unroll
        for (int o = 16; o; o >>= 1) ls += __shfl_xor_sync(0xffffffffu, ls, o);
        if (lid == 0) sinv[ni] = 1.f / ls;
    }
    __syncthreads();

    // ---- phase B: warp = (ch, fn, ks-half); each warp covers all 4 fd ----
    const int ch = w & 3;
    const int fn = (w >> 2) & 1;
    const int kh = w >> 3;
    const u32 varr = (ch == 0) ? 2u : 0u;
    float acc[4][4];
#pragma unroll
    for (int fd = 0; fd < 4; fd++)
#pragma unroll
        for (int q = 0; q < 4; q++) acc[fd][q] = 0.f;

    const float4* pdg = g_pd + (u64)(b*Nn + n0)*EXTm;
    const int pd_ni0 = t >> 5,          pd_ml0 = (t & 31)*2;
    const int pd_ni1 = (t + 512) >> 5,  pd_ml1 = ((t + 512) & 31)*2;

    for (int mt = 0; mt < 12; mt++) {
        int s = mt & 1;
        u32 wst = (u32)(oW + s*36864);
        // weight build into W[s]; p normalized here via sinv
#pragma unroll
        for (int jj = 0; jj < 2; jj++) {
            int ni = jj ? pd_ni1 : pd_ni0;
            int ml = jj ? pd_ml1 : pd_ml0;
            float4 d0 = pdg[(u64)ni*EXTm + mt*64 + ml];
            float4 d1 = pdg[(u64)ni*EXTm + mt*64 + ml + 1];
            float inv = sinv[ni];
            float2 pp = *(float2*)&S[ni*SPITCH + mt*64 + ml];
            pp.x *= inv; pp.y *= inv;
            float wsa[4] = { pp.x, pp.x*d0.x, pp.x*d0.y, pp.x*d0.z };
            float wsb[4] = { pp.y, pp.y*d1.x, pp.y*d1.y, pp.y*d1.z };
#pragma unroll
            for (int c = 0; c < 4; c++) {
                __nv_bfloat16 ha = __float2bfloat16(wsa[c]);
                __nv_bfloat16 hb = __float2bfloat16(wsb[c]);
                __nv_bfloat16 la = __float2bfloat16(wsa[c] - __bfloat162float(ha));
                __nv_bfloat16 lb = __float2bfloat16(wsb[c] - __bfloat162float(hb));
                *(__nv_bfloat162*)(sm + wst + c*4608 + ni*144 + ml*2)         = __halves2bfloat162(ha, hb);
                *(__nv_bfloat162*)(sm + wst + 18432 + c*4608 + ni*144 + ml*2) = __halves2bfloat162(la, lb);
            }
        }
        asm volatile("cp.async.wait_group 0;" ::: "memory");
        __syncthreads();
        if (mt < 11) ISSUE_V(mt + 1, s ^ 1);
        u32 vbase = smb + oV + s*20480;
#pragma unroll
        for (int ks2 = 0; ks2 < 2; ks2++) {
            int ks = kh*2 + ks2;
            u32 wa = wst + ch*4608 + (fn*16 + aoff)*144 + acol + ks*32;
            u32 ah[4], al[4];
            ldsm4(ah, smb + wa); ldsm4(al, smb + wa + 18432);
            u32 vrow = (u32)(ks*16 + (lid & 15));
#pragma unroll
            for (int fd = 0; fd < 4; fd++) {
                u32 va = vbase + varr*5120 + vrow*80 + fd*16;
                u32 bh[2], bl[2];
                ldsm2t(bh, va);
                ldsm2t(bl, va + 5120);
                mma16816(acc[fd], ah, bh[0], bh[1]);
                mma16816(acc[fd], al, bh[0], bh[1]);
                mma16816(acc[fd], ah, bl[0], bl[1]);
            }
        }
    }

    // ---- cross-kh reduction (partners w and w^8) via smem scratch at oW ----
    __syncthreads();
    float* scratch = (float*)(sm + oW);
    if (kh == 1) {
        int w8 = w & 7;
#pragma unroll
        for (int fd = 0; fd < 4; fd++)
            *(float4*)&scratch[((w8*4 + fd)*32 + lid)*4] =
                make_float4(acc[fd][0], acc[fd][1], acc[fd][2], acc[fd][3]);
    }
    __syncthreads();
    if (kh == 0) {
        int gid = lid >> 2, tig = lid & 3;
#pragma unroll
        for (int fd = 0; fd < 4; fd++) {
            float4 o = *(float4*)&scratch[((w*4 + fd)*32 + lid)*4];
            float2 v0 = make_float2(acc[fd][0] + o.x, acc[fd][1] + o.y);
            float2 v1 = make_float2(acc[fd][2] + o.z, acc[fd][3] + o.w);
            int col = h*32 + fd*8 + tig*2;
            int r0 = n0 + fn*16 + gid;
            int r1 = r0 + 8;
            u64 row0g, row1g;
            if (ch == 0) {
                row0g = (u64)(b*Nn + r0);
                row1g = (u64)(b*Nn + r1);
            } else {
                row0g = 2048 + ((u64)(b*Nn + r0)*3 + (ch-1));
                row1g = 2048 + ((u64)(b*Nn + r1)*3 + (ch-1));
            }
            st_hilo(g_ah, g_al, row0g*Ee + col, v0);
            st_hilo(g_ah, g_al, row1g*Ee + col, v1);
        }
    }
}

// ---------------- host entry ----------------
extern "C" void kernel_launch(void* const* d_in, const int* in_sizes, int n_in,
                              void* d_out, int out_size)
{
    const float* x    = (const float*)d_in[0];
    const float* pos  = (const float*)d_in[1];
    const float* epos = (const float*)d_in[2];
    const float* bias = (const float*)d_in[3];
    const unsigned char* pmask = (const unsigned char*)d_in[4];
    const unsigned char* emask = (const unsigned char*)d_in[5];
    const int*   idx  = (const int*)d_in[6];
    const float* Wq   = (const float*)d_in[7];
    const float* Wk   = (const float*)d_in[8];
    const float* Wv   = (const float*)d_in[9];
    const float* Wve  = (const float*)d_in[10];
    const float* Wo   = (const float*)d_in[11];
    const float* Woe  = (const float*)d_in[12];
    float* out = (float*)d_out;

    cudaFuncSetAttribute(mm_mma, cudaFuncAttributeMaxDynamicSharedMemorySize, MM_SMEM);
    cudaFuncSetAttribute(attn_mma, cudaFuncAttributeMaxDynamicSharedMemorySize, ATTN_SMEM);

    prep_kernel<<<10240, 256>>>(x, pos, epos, pmask, emask, Wq, Wk, Wv, Wve, Woe, Wo);

    mm_mma<<<dim3(8, 16, 4), 256, MM_SMEM>>>(nullptr, 0);    // q,k,v,ve projections

    gather_kernel<<<Bb*Mm, 256>>>(idx);

    attn_mma<<<dim3(8, 32, 8), 512, ATTN_SMEM>>>(bias, pmask, emask);

    mm_mma<<<dim3(8, 64, 1), 256, MM_SMEM>>>(out, 6);        // merged xo@Woe + vec@Wo
}